// round 4
// baseline (speedup 1.0000x reference)
#include <cuda_runtime.h>
#include <cuda_bf16.h>
#include <math.h>

// Problem constants
#define T_TOKENS   16384
#define HID        4096
#define NEXP       64
#define TOPK       8
#define RSCALE     2.5f

// Tiling
#define TM    128           // tokens per block
#define KB    32            // k-chunk per smem stage (also the TwoSum super-chunk)
#define NTH   512           // threads per block (16 warps)
#define NKT   (HID / KB)    // 128 k-tiles

typedef unsigned long long ull;

__device__ __forceinline__ ull ffma2(ull a, ull b, ull c) {
    ull d;
    asm("fma.rn.f32x2 %0, %1, %2, %3;" : "=l"(d) : "l"(a), "l"(b), "l"(c));
    return d;
}
__device__ __forceinline__ ull add2(ull a, ull b) {
    ull d;
    asm("add.rn.f32x2 %0, %1, %2;" : "=l"(d) : "l"(a), "l"(b));
    return d;
}
__device__ __forceinline__ ull pack2(float x) {
    ull d;
    asm("mov.b64 %0, {%1, %1};" : "=l"(d) : "f"(x));
    return d;
}
__device__ __forceinline__ void unpack2(ull v, float& lo, float& hi) {
    asm("mov.b64 {%0, %1}, %2;" : "=f"(lo), "=f"(hi) : "l"(v));
}
// packed lanewise a - b = fma(b, -1, a)  (exact)
__device__ __forceinline__ ull sub2(ull a, ull b, ull NEG1) {
    return ffma2(b, NEG1, a);
}

struct Stage {
    float xs[KB][TM];     // x transposed: xs[k][token]   (row = 512B, bank-aligned)
    float ws[KB][NEXP];   // W tile:       ws[k][expert]
};

__global__ __launch_bounds__(NTH, 1)
void moe_gate_kernel(const float* __restrict__ x,
                     const float* __restrict__ W,
                     const float* __restrict__ bias,
                     float* __restrict__ out)
{
    // 2-stage pipeline buffers union'd with the epilogue score matrix. 48KB exactly.
    __shared__ union SM {
        Stage st[2];                                         // 2 * 24576 = 49152 B
        struct { float sc[TM][NEXP + 1]; float bias[NEXP]; } e; // 33536 B
    } sm;

    const int tid = threadIdx.x;
    const int tx  = tid & 7;     // experts [tx*8, tx*8+8)
    const int tyg = tid >> 3;    // token pair: tokens {tyg*2, tyg*2+1}
    const int t0  = blockIdx.x * TM;
    const float* xg = x + (size_t)t0 * HID;

    // prefetch mapping: x tile = 1024 float4 (2 per thread), W tile = 512 float4 (1 per thread)
    const int xf0   = tid * 2;
    const int xtok0 = xf0 >> 3;
    const int xk0   = (xf0 & 7) * 4;
    const int xf1   = xf0 + 1;
    const int xtok1 = xf1 >> 3;
    const int xk1   = (xf1 & 7) * 4;
    const int wrow  = tid >> 4;
    const int wcol  = (tid & 15) * 4;

    // ---- prologue: fill stage 0
    {
        float4 v0 = *(const float4*)(xg + (size_t)xtok0 * HID + xk0);
        float4 v1 = *(const float4*)(xg + (size_t)xtok1 * HID + xk1);
        float4 wv = *(const float4*)(W + (size_t)wrow * NEXP + wcol);
        Stage& N = sm.st[0];
        N.xs[xk0 + 0][xtok0] = v0.x;  N.xs[xk0 + 1][xtok0] = v0.y;
        N.xs[xk0 + 2][xtok0] = v0.z;  N.xs[xk0 + 3][xtok0] = v0.w;
        N.xs[xk1 + 0][xtok1] = v1.x;  N.xs[xk1 + 1][xtok1] = v1.y;
        N.xs[xk1 + 2][xtok1] = v1.z;  N.xs[xk1 + 3][xtok1] = v1.w;
        *(float4*)&N.ws[wrow][wcol] = wv;
    }

    const ull NEG1 = pack2(-1.0f);

    // compensated accumulators: 2 tokens x 4 expert-pairs
    ull s[2][4], c[2][4];
    #pragma unroll
    for (int i = 0; i < 2; ++i)
        #pragma unroll
        for (int j = 0; j < 4; ++j) { s[i][j] = 0ull; c[i][j] = 0ull; }

    for (int kt = 0; kt < NKT; ++kt) {
        // ---- prefetch next tile into registers (latency hidden under compute)
        float4 pv0, pv1, pw;
        const bool pf = (kt + 1 < NKT);
        if (pf) {
            const float* xb = xg + (kt + 1) * KB;
            pv0 = *(const float4*)(xb + (size_t)xtok0 * HID + xk0);
            pv1 = *(const float4*)(xb + (size_t)xtok1 * HID + xk1);
            pw  = *(const float4*)(W + (size_t)((kt + 1) * KB + wrow) * NEXP + wcol);
        }
        __syncthreads();   // single barrier per kt: stage (kt&1) fully written, safe to read
        const Stage& S = sm.st[kt & 1];

        // ---- compute: 4 independent 8-term FFMA2 chains per accumulator,
        //      combined with plain add2 (tree-ish), one TwoSum per 32 terms.
        ull u[2][4];
        #pragma unroll
        for (int sub = 0; sub < 4; ++sub) {
            ull t[2][4];
            #pragma unroll
            for (int i = 0; i < 2; ++i)
                #pragma unroll
                for (int j = 0; j < 4; ++j) t[i][j] = 0ull;

            #pragma unroll
            for (int q = 0; q < 8; ++q) {
                const int kk = sub * 8 + q;
                float2 a2 = *(const float2*)&S.xs[kk][tyg * 2];
                ull a0 = pack2(a2.x);
                ull a1 = pack2(a2.y);
                ulonglong2 b01 = *(const ulonglong2*)&S.ws[kk][tx * 8];
                ulonglong2 b23 = *(const ulonglong2*)&S.ws[kk][tx * 8 + 4];
                ull b[4] = {b01.x, b01.y, b23.x, b23.y};
                #pragma unroll
                for (int j = 0; j < 4; ++j) {
                    t[0][j] = ffma2(a0, b[j], t[0][j]);
                    t[1][j] = ffma2(a1, b[j], t[1][j]);
                }
            }
            #pragma unroll
            for (int i = 0; i < 2; ++i)
                #pragma unroll
                for (int j = 0; j < 4; ++j)
                    u[i][j] = (sub == 0) ? t[i][j] : add2(u[i][j], t[i][j]);
        }

        // TwoSum: (s, c) += u   (branchless Knuth, lanewise packed)
        #pragma unroll
        for (int i = 0; i < 2; ++i)
            #pragma unroll
            for (int j = 0; j < 4; ++j) {
                ull sp = add2(s[i][j], u[i][j]);
                ull z  = sub2(sp, s[i][j], NEG1);
                ull e1 = sub2(u[i][j], z, NEG1);
                ull t2 = sub2(sp, z, NEG1);
                ull e2 = sub2(s[i][j], t2, NEG1);
                c[i][j] = add2(c[i][j], add2(e1, e2));
                s[i][j] = sp;
            }

        // ---- store prefetched tile into the other stage (no barrier needed here;
        //      next iteration's syncthreads publishes it)
        if (pf) {
            Stage& N = sm.st[(kt + 1) & 1];
            N.xs[xk0 + 0][xtok0] = pv0.x;  N.xs[xk0 + 1][xtok0] = pv0.y;
            N.xs[xk0 + 2][xtok0] = pv0.z;  N.xs[xk0 + 3][xtok0] = pv0.w;
            N.xs[xk1 + 0][xtok1] = pv1.x;  N.xs[xk1 + 1][xtok1] = pv1.y;
            N.xs[xk1 + 2][xtok1] = pv1.z;  N.xs[xk1 + 3][xtok1] = pv1.w;
            *(float4*)&N.ws[wrow][wcol] = pw;
        }
    }

    __syncthreads();  // all stage reads done; union now reused as score matrix

    // ---- epilogue: logits = s + c, sigmoid, write scores
    #pragma unroll
    for (int i = 0; i < 2; ++i) {
        int tok = tyg * 2 + i;
        #pragma unroll
        for (int j = 0; j < 4; ++j) {
            float lo, hi;
            unpack2(add2(s[i][j], c[i][j]), lo, hi);
            int e = tx * 8 + 2 * j;
            sm.e.sc[tok][e]     = 1.0f / (1.0f + expf(-lo));
            sm.e.sc[tok][e + 1] = 1.0f / (1.0f + expf(-hi));
        }
    }
    if (tid < NEXP) sm.e.bias[tid] = bias[tid];
    __syncthreads();

    // ---- top-8 per token (stable: ties keep lowest expert index first)
    if (tid < TM) {
        const int tok = tid;
        float bv[TOPK];
        int   bi[TOPK];
        #pragma unroll
        for (int k = 0; k < TOPK; ++k) { bv[k] = -INFINITY; bi[k] = 0; }

        for (int e = 0; e < NEXP; ++e) {
            float sv = sm.e.sc[tok][e] + sm.e.bias[e];
            if (sv > bv[TOPK - 1]) {
                bv[TOPK - 1] = sv; bi[TOPK - 1] = e;
                #pragma unroll
                for (int j = TOPK - 1; j > 0; --j) {
                    if (bv[j] > bv[j - 1]) {
                        float tv = bv[j]; bv[j] = bv[j - 1]; bv[j - 1] = tv;
                        int   ti = bi[j]; bi[j] = bi[j - 1]; bi[j - 1] = ti;
                    }
                }
            }
        }

        float wsel[TOPK];
        float sum = 1e-20f;
        #pragma unroll
        for (int k = 0; k < TOPK; ++k) {
            wsel[k] = sm.e.sc[tok][bi[k]];
            sum += wsel[k];
        }
        float inv = RSCALE / sum;

        const size_t gt = (size_t)(t0 + tok);
        float* out_idx = out + gt * TOPK;
        float* out_w   = out + (size_t)T_TOKENS * TOPK + gt * TOPK;
        #pragma unroll
        for (int k = 0; k < TOPK; ++k) {
            out_idx[k] = (float)bi[k];
            out_w[k]   = wsel[k] * inv;
        }
    }
}

extern "C" void kernel_launch(void* const* d_in, const int* in_sizes, int n_in,
                              void* d_out, int out_size)
{
    const float* x    = (const float*)d_in[0];
    const float* W    = (const float*)d_in[1];
    const float* bias = (const float*)d_in[2];
    float* out = (float*)d_out;

    dim3 grid(T_TOKENS / TM);
    dim3 block(NTH);
    moe_gate_kernel<<<grid, block>>>(x, W, bias, out);
}

// round 5
// speedup vs baseline: 2.0966x; 2.0966x over previous
#include <cuda_runtime.h>
#include <cuda_bf16.h>
#include <math.h>

// Problem constants
#define T_TOKENS   16384
#define HID        4096
#define NEXP       64
#define TOPK       8
#define RSCALE     2.5f

// Tiling
#define TM    128           // tokens per block
#define KB    32            // k-chunk per smem stage (TwoSum super-chunk)
#define NTH   512           // threads per block (16 warps)
#define NKT   (HID / KB)    // 128 k-tiles

typedef unsigned long long ull;

__device__ __forceinline__ ull ffma2(ull a, ull b, ull c) {
    ull d;
    asm("fma.rn.f32x2 %0, %1, %2, %3;" : "=l"(d) : "l"(a), "l"(b), "l"(c));
    return d;
}
__device__ __forceinline__ ull add2(ull a, ull b) {
    ull d;
    asm("add.rn.f32x2 %0, %1, %2;" : "=l"(d) : "l"(a), "l"(b));
    return d;
}
__device__ __forceinline__ ull pack2(float x) {
    ull d;
    asm("mov.b64 %0, {%1, %1};" : "=l"(d) : "f"(x));
    return d;
}
__device__ __forceinline__ void unpack2(ull v, float& lo, float& hi) {
    asm("mov.b64 {%0, %1}, %2;" : "=f"(lo), "=f"(hi) : "l"(v));
}
// packed lanewise a - b = fma(b, -1, a)  (exact)
__device__ __forceinline__ ull sub2(ull a, ull b, ull NEG1) {
    return ffma2(b, NEG1, a);
}

struct Stage {
    float xs[KB][TM];     // x transposed: xs[k][token]  (row = 512B)
    float ws[KB][NEXP];   // W tile:       ws[k][expert] (row = 256B)
};

__global__ __launch_bounds__(NTH, 1)
void moe_gate_kernel(const float* __restrict__ x,
                     const float* __restrict__ W,
                     const float* __restrict__ bias,
                     float* __restrict__ out)
{
    // 2-stage pipeline buffers union'd with the epilogue score matrix.
    __shared__ union SM {
        Stage st[2];                                            // 49152 B
        struct { float sc[TM][NEXP + 1]; float bias[NEXP]; } e; // 33536 B
    } sm;

    const int tid  = threadIdx.x;
    const int lane = tid & 31;
    const int wid  = tid >> 5;          // 0..15
    const int tok0 = wid * 8;           // warp's 8 tokens
    const int e0   = lane;              // this lane's experts: e0, e0+32
    const int t0   = blockIdx.x * TM;
    const float* xg = x + (size_t)t0 * HID;

    // prefetch mapping: x tile = 1024 float4 (2/thread), W tile = 512 float4 (1/thread)
    const int xf0   = tid * 2;
    const int xtok0 = xf0 >> 3;
    const int xk0   = (xf0 & 7) * 4;
    const int xf1   = xf0 + 1;
    const int xtok1 = xf1 >> 3;
    const int xk1   = (xf1 & 7) * 4;
    const int wrow  = tid >> 4;
    const int wcol  = (tid & 15) * 4;

    // ---- prologue: fill stage 0
    {
        float4 v0 = *(const float4*)(xg + (size_t)xtok0 * HID + xk0);
        float4 v1 = *(const float4*)(xg + (size_t)xtok1 * HID + xk1);
        float4 wv = *(const float4*)(W + (size_t)wrow * NEXP + wcol);
        Stage& N = sm.st[0];
        N.xs[xk0 + 0][xtok0] = v0.x;  N.xs[xk0 + 1][xtok0] = v0.y;
        N.xs[xk0 + 2][xtok0] = v0.z;  N.xs[xk0 + 3][xtok0] = v0.w;
        N.xs[xk1 + 0][xtok1] = v1.x;  N.xs[xk1 + 1][xtok1] = v1.y;
        N.xs[xk1 + 2][xtok1] = v1.z;  N.xs[xk1 + 3][xtok1] = v1.w;
        *(float4*)&N.ws[wrow][wcol] = wv;
    }

    const ull NEG1 = pack2(-1.0f);

    // compensated accumulators: 4 token-pairs x 2 experts, packed over tokens
    // s[p][j] lanes = logits(tok0+2p, e_j), (tok0+2p+1, e_j)  with e_0=e0, e_1=e0+32
    ull s[4][2], c[4][2];
    #pragma unroll
    for (int p = 0; p < 4; ++p)
        #pragma unroll
        for (int j = 0; j < 2; ++j) { s[p][j] = 0ull; c[p][j] = 0ull; }

    for (int kt = 0; kt < NKT; ++kt) {
        // ---- prefetch next tile into registers
        float4 pv0, pv1, pw;
        const bool pf = (kt + 1 < NKT);
        if (pf) {
            const float* xb = xg + (kt + 1) * KB;
            pv0 = *(const float4*)(xb + (size_t)xtok0 * HID + xk0);
            pv1 = *(const float4*)(xb + (size_t)xtok1 * HID + xk1);
            pw  = *(const float4*)(W + (size_t)((kt + 1) * KB + wrow) * NEXP + wcol);
        }
        __syncthreads();   // stage (kt&1) published
        const Stage& S = sm.st[kt & 1];

        // ---- compute: 4 independent 8-term FFMA2 chains per accumulator,
        //      plain add2 tree combine, one TwoSum per 32 terms (validated numerics)
        ull u[4][2];
        #pragma unroll
        for (int sub = 0; sub < 4; ++sub) {
            ull t[4][2];
            #pragma unroll
            for (int p = 0; p < 4; ++p)
                #pragma unroll
                for (int j = 0; j < 2; ++j) t[p][j] = 0ull;

            #pragma unroll
            for (int q = 0; q < 8; ++q) {
                const int kk = sub * 8 + q;
                // ws: lane-consecutive scalars -> conflict-free 1-wf LDS.32
                float w0 = S.ws[kk][e0];
                float w1 = S.ws[kk][e0 + 32];
                ull b0 = pack2(w0);
                ull b1 = pack2(w1);
                // xs: warp-uniform address -> true broadcast (free)
                ulonglong2 xa = *(const ulonglong2*)&S.xs[kk][tok0];
                ulonglong2 xb2 = *(const ulonglong2*)&S.xs[kk][tok0 + 4];
                ull a[4] = {xa.x, xa.y, xb2.x, xb2.y};   // packed token-pairs
                #pragma unroll
                for (int p = 0; p < 4; ++p) {
                    t[p][0] = ffma2(a[p], b0, t[p][0]);
                    t[p][1] = ffma2(a[p], b1, t[p][1]);
                }
            }
            #pragma unroll
            for (int p = 0; p < 4; ++p)
                #pragma unroll
                for (int j = 0; j < 2; ++j)
                    u[p][j] = (sub == 0) ? t[p][j] : add2(u[p][j], t[p][j]);
        }

        // TwoSum: (s, c) += u   (branchless Knuth, lanewise packed)
        #pragma unroll
        for (int p = 0; p < 4; ++p)
            #pragma unroll
            for (int j = 0; j < 2; ++j) {
                ull sp = add2(s[p][j], u[p][j]);
                ull z  = sub2(sp, s[p][j], NEG1);
                ull e1 = sub2(u[p][j], z, NEG1);
                ull t2 = sub2(sp, z, NEG1);
                ull e2 = sub2(s[p][j], t2, NEG1);
                c[p][j] = add2(c[p][j], add2(e1, e2));
                s[p][j] = sp;
            }

        // ---- store prefetched tile into the other stage
        if (pf) {
            Stage& N = sm.st[(kt + 1) & 1];
            N.xs[xk0 + 0][xtok0] = pv0.x;  N.xs[xk0 + 1][xtok0] = pv0.y;
            N.xs[xk0 + 2][xtok0] = pv0.z;  N.xs[xk0 + 3][xtok0] = pv0.w;
            N.xs[xk1 + 0][xtok1] = pv1.x;  N.xs[xk1 + 1][xtok1] = pv1.y;
            N.xs[xk1 + 2][xtok1] = pv1.z;  N.xs[xk1 + 3][xtok1] = pv1.w;
            *(float4*)&N.ws[wrow][wcol] = pw;
        }
    }

    __syncthreads();  // stage reads done; union becomes score matrix

    // ---- epilogue: logits = s + c, sigmoid, write scores
    #pragma unroll
    for (int p = 0; p < 4; ++p) {
        #pragma unroll
        for (int j = 0; j < 2; ++j) {
            float lo, hi;
            unpack2(add2(s[p][j], c[p][j]), lo, hi);
            const int e = e0 + j * 32;
            sm.e.sc[tok0 + 2 * p    ][e] = 1.0f / (1.0f + expf(-lo));
            sm.e.sc[tok0 + 2 * p + 1][e] = 1.0f / (1.0f + expf(-hi));
        }
    }
    if (tid < NEXP) sm.e.bias[tid] = bias[tid];
    __syncthreads();

    // ---- top-8 per token (stable: ties keep lowest expert index first)
    if (tid < TM) {
        const int tok = tid;
        float bv[TOPK];
        int   bi[TOPK];
        #pragma unroll
        for (int k = 0; k < TOPK; ++k) { bv[k] = -INFINITY; bi[k] = 0; }

        for (int e = 0; e < NEXP; ++e) {
            float sv = sm.e.sc[tok][e] + sm.e.bias[e];
            if (sv > bv[TOPK - 1]) {
                bv[TOPK - 1] = sv; bi[TOPK - 1] = e;
                #pragma unroll
                for (int j = TOPK - 1; j > 0; --j) {
                    if (bv[j] > bv[j - 1]) {
                        float tv = bv[j]; bv[j] = bv[j - 1]; bv[j - 1] = tv;
                        int   ti = bi[j]; bi[j] = bi[j - 1]; bi[j - 1] = ti;
                    }
                }
            }
        }

        float wsel[TOPK];
        float sum = 1e-20f;
        #pragma unroll
        for (int k = 0; k < TOPK; ++k) {
            wsel[k] = sm.e.sc[tok][bi[k]];
            sum += wsel[k];
        }
        float inv = RSCALE / sum;

        const size_t gt = (size_t)(t0 + tok);
        float* out_idx = out + gt * TOPK;
        float* out_w   = out + (size_t)T_TOKENS * TOPK + gt * TOPK;
        #pragma unroll
        for (int k = 0; k < TOPK; ++k) {
            out_idx[k] = (float)bi[k];
            out_w[k]   = wsel[k] * inv;
        }
    }
}

extern "C" void kernel_launch(void* const* d_in, const int* in_sizes, int n_in,
                              void* d_out, int out_size)
{
    const float* x    = (const float*)d_in[0];
    const float* W    = (const float*)d_in[1];
    const float* bias = (const float*)d_in[2];
    float* out = (float*)d_out;

    dim3 grid(T_TOKENS / TM);
    dim3 block(NTH);
    moe_gate_kernel<<<grid, block>>>(x, W, bias, out);
}